// round 11
// baseline (speedup 1.0000x reference)
#include <cuda_runtime.h>

// LR_23029614641373: logit = W[u] + W[6040+m] + b; out = [1-p, p]
// Base = R10 (ncu 13.2us, best): SMEM table + exp+rcp sigmoid + depth-2
// rotating software pipeline at 512 threads (compiled to 31 regs).
// SINGLE CHANGE this round: NBLK_SM 3 -> 4 (launch_bounds cap 32 regs,
// non-binding at the measured 31). Restores occupancy 67% -> ~88%,
// raising chip-wide in-flight bytes by ~1/3 — the same constraint the
// depth-2 change already moved (issue 41->48%, HBM 2.4->2.57TB/s).

#define N_USERS 6040
#define TABLE   9923
#define NTHREADS 512
#define NBLK_SM  4

__global__ void __launch_bounds__(NTHREADS, NBLK_SM) lr_smem_kernel(
    const int4* __restrict__ x2,      // [n2] two (u,m) rows per int4
    const float* __restrict__ w,      // [9923]
    const float* __restrict__ bptr,   // [1]
    float4* __restrict__ out,         // [n2] {1-p0,p0,1-p1,p1}
    int n2)
{
    __shared__ float sw[TABLE];
    #pragma unroll
    for (int i = threadIdx.x; i < TABLE; i += NTHREADS)
        sw[i] = w[i];
    __syncthreads();

    const float bias = __ldg(bptr);
    const int stride = gridDim.x * blockDim.x;

    int i = blockIdx.x * blockDim.x + threadIdx.x;
    if (i >= n2) return;

    // depth-2 rotating pipeline: while computing v (index i), loads for
    // i1 and i2 are in flight.
    int4 v = x2[i];
    int i1 = i + stride;
    int4 v1;
    bool h1 = (i1 < n2);
    if (h1) v1 = x2[i1];

    while (true) {
        int i2 = i1 + stride;
        int4 v2;
        bool h2 = h1 && (i2 < n2);
        if (h2) v2 = x2[i2];             // prefetch two iterations ahead

        float l0 = sw[v.x] + sw[N_USERS + v.y] + bias;
        float l1 = sw[v.z] + sw[N_USERS + v.w] + bias;

        // p = 1/(1+e^-l);  1-p = e^-l * p
        float e0 = __expf(-l0);
        float e1 = __expf(-l1);
        float p0 = __frcp_rn(1.0f + e0);
        float p1 = __frcp_rn(1.0f + e1);

        out[i] = make_float4(e0 * p0, p0, e1 * p1, p1);

        if (!h1) break;
        i = i1;  v = v1;
        i1 = i2; v1 = v2; h1 = h2;
    }
}

// Rare odd-row tail (B is even in this dataset).
__global__ void lr_tail_kernel(
    const int2* __restrict__ x,
    const float* __restrict__ w,
    const float* __restrict__ bptr,
    float2* __restrict__ out,
    int start, int n)
{
    int i = start + blockIdx.x * blockDim.x + threadIdx.x;
    if (i >= n) return;
    int2 v = x[i];
    float l = __ldg(w + v.x) + __ldg(w + N_USERS + v.y) + __ldg(bptr);
    float e = __expf(-l);
    float p = __frcp_rn(1.0f + e);
    out[i] = make_float2(e * p, p);
}

extern "C" void kernel_launch(void* const* d_in, const int* in_sizes, int n_in,
                              void* d_out, int out_size)
{
    const int*   x = (const int*)d_in[0];     // [B, 2] int32
    const float* W = (const float*)d_in[1];   // [1, 9923]
    const float* b = (const float*)d_in[2];   // [1]
    float* out = (float*)d_out;               // [B, 2]

    int B  = in_sizes[0] / 2;
    int n2 = B / 2;

    if (n2 > 0) {
        int max_blocks = 148 * NBLK_SM;       // 592
        int blocks = (n2 + NTHREADS - 1) / NTHREADS;
        if (blocks > max_blocks) blocks = max_blocks;
        lr_smem_kernel<<<blocks, NTHREADS>>>(
            (const int4*)x, W, b, (float4*)out, n2);
    }
    if (B & 1) {
        lr_tail_kernel<<<1, 32>>>(
            (const int2*)x, W, b, (float2*)out, 2 * n2, B);
    }
}

// round 12
// speedup vs baseline: 1.0769x; 1.0769x over previous
#include <cuda_runtime.h>

// LR_23029614641373: logit = W[u] + W[6040+m] + b; out = [1-p, p]
// Base = R10 (ncu 13.2us best): SMEM table + exp+rcp + software pipeline,
// 512 threads. SINGLE CHANGE: pipeline stage width 1 -> 2 int4 (process
// i and i+stride per stage, prefetch i+2s/i+3s). Amortizes rotation MOVs,
// index math and branch over 2x work — R11 showed occupancy is not the
// constraint (67->81% occ made it slightly worse), pointing at per-warp
// issue overhead instead. launch_bounds(512,3): 40-reg budget for the
// wider stage, occupancy pinned at R10's measured-best 67%.

#define N_USERS 6040
#define TABLE   9923
#define NTHREADS 512
#define NBLK_SM  3

__device__ __forceinline__ float4 two_rows_exp(const float* __restrict__ sw,
                                               int4 v, float bias) {
    float l0 = sw[v.x] + sw[N_USERS + v.y] + bias;
    float l1 = sw[v.z] + sw[N_USERS + v.w] + bias;
    float e0 = __expf(-l0);
    float e1 = __expf(-l1);
    float p0 = __frcp_rn(1.0f + e0);
    float p1 = __frcp_rn(1.0f + e1);
    return make_float4(e0 * p0, p0, e1 * p1, p1);
}

__global__ void __launch_bounds__(NTHREADS, NBLK_SM) lr_smem_kernel(
    const int4* __restrict__ x2,      // [n2] two (u,m) rows per int4
    const float* __restrict__ w,      // [9923]
    const float* __restrict__ bptr,   // [1]
    float4* __restrict__ out,         // [n2] {1-p0,p0,1-p1,p1}
    int n2)
{
    __shared__ float sw[TABLE];
    #pragma unroll
    for (int i = threadIdx.x; i < TABLE; i += NTHREADS)
        sw[i] = w[i];
    __syncthreads();

    const float bias = __ldg(bptr);
    const int stride = gridDim.x * blockDim.x;

    int i0 = blockIdx.x * blockDim.x + threadIdx.x;
    if (i0 >= n2) return;

    // current stage: (i0, i1); prefetched stage: (j0, j1)
    int  i1 = i0 + stride;
    int4 v0 = x2[i0];
    int4 v1;
    bool a1 = (i1 < n2);
    if (a1) v1 = x2[i1];

    while (true) {
        int j0 = i0 + 2 * stride;
        int j1 = i0 + 3 * stride;
        int4 w0, w1;
        bool b0 = (j0 < n2);
        bool b1 = (j1 < n2);
        if (b0) w0 = x2[j0];            // prefetch next stage (2 loads)
        if (b1) w1 = x2[j1];

        out[i0] = two_rows_exp(sw, v0, bias);
        if (a1) out[i1] = two_rows_exp(sw, v1, bias);

        if (!b0) break;
        i0 = j0; i1 = j1;
        v0 = w0; v1 = w1;
        a1 = b1;
    }
}

// Rare odd-row tail (B is even in this dataset).
__global__ void lr_tail_kernel(
    const int2* __restrict__ x,
    const float* __restrict__ w,
    const float* __restrict__ bptr,
    float2* __restrict__ out,
    int start, int n)
{
    int i = start + blockIdx.x * blockDim.x + threadIdx.x;
    if (i >= n) return;
    int2 v = x[i];
    float l = __ldg(w + v.x) + __ldg(w + N_USERS + v.y) + __ldg(bptr);
    float e = __expf(-l);
    float p = __frcp_rn(1.0f + e);
    out[i] = make_float2(e * p, p);
}

extern "C" void kernel_launch(void* const* d_in, const int* in_sizes, int n_in,
                              void* d_out, int out_size)
{
    const int*   x = (const int*)d_in[0];     // [B, 2] int32
    const float* W = (const float*)d_in[1];   // [1, 9923]
    const float* b = (const float*)d_in[2];   // [1]
    float* out = (float*)d_out;               // [B, 2]

    int B  = in_sizes[0] / 2;
    int n2 = B / 2;

    if (n2 > 0) {
        int max_blocks = 148 * NBLK_SM;       // 444
        int blocks = (n2 + NTHREADS - 1) / NTHREADS;
        if (blocks > max_blocks) blocks = max_blocks;
        lr_smem_kernel<<<blocks, NTHREADS>>>(
            (const int4*)x, W, b, (float4*)out, n2);
    }
    if (B & 1) {
        lr_tail_kernel<<<1, 32>>>(
            (const int2*)x, W, b, (float2*)out, 2 * n2, B);
    }
}

// round 13
// speedup vs baseline: 1.1228x; 1.0426x over previous
#include <cuda_runtime.h>

// LR_23029614641373: logit = W[u] + W[6040+m] + b; out = [1-p, p]
// Lineage: R10 depth-2 pipeline (ncu 13.2) -> R12 stage-width 2 (ncu 12.6,
// wall 13.3 best). SINGLE CHANGE: stage width 2 -> 4 int4 per pipeline
// stage (4 independent LDG.128 in flight per warp; per-stage loop
// overhead amortized over 4x work). launch_bounds(512,2): 64-reg budget
// so the 4-wide rotation never spills; R11/R12 proved occupancy >64% is
// not the constraint.

#define N_USERS 6040
#define TABLE   9923
#define NTHREADS 512
#define NBLK_SM  2
#define WIDTH    4

__device__ __forceinline__ float4 two_rows_exp(const float* __restrict__ sw,
                                               int4 v, float bias) {
    float l0 = sw[v.x] + sw[N_USERS + v.y] + bias;
    float l1 = sw[v.z] + sw[N_USERS + v.w] + bias;
    float e0 = __expf(-l0);
    float e1 = __expf(-l1);
    float p0 = __frcp_rn(1.0f + e0);
    float p1 = __frcp_rn(1.0f + e1);
    return make_float4(e0 * p0, p0, e1 * p1, p1);
}

__global__ void __launch_bounds__(NTHREADS, NBLK_SM) lr_smem_kernel(
    const int4* __restrict__ x2,      // [n2] two (u,m) rows per int4
    const float* __restrict__ w,      // [9923]
    const float* __restrict__ bptr,   // [1]
    float4* __restrict__ out,         // [n2] {1-p0,p0,1-p1,p1}
    int n2)
{
    __shared__ float sw[TABLE];
    #pragma unroll
    for (int i = threadIdx.x; i < TABLE; i += NTHREADS)
        sw[i] = w[i];
    __syncthreads();

    const float bias = __ldg(bptr);
    const int stride = gridDim.x * blockDim.x;

    int base = blockIdx.x * blockDim.x + threadIdx.x;
    if (base >= n2) return;

    // current stage indices: base + k*stride, k=0..3
    int4 v[WIDTH];
    bool a[WIDTH];
    #pragma unroll
    for (int k = 0; k < WIDTH; k++) {
        int idx = base + k * stride;
        a[k] = (idx < n2);
        if (a[k]) v[k] = x2[idx];
    }

    while (true) {
        int nbase = base + WIDTH * stride;

        // prefetch next stage (up to 4 independent coalesced LDG.128)
        int4 nv[WIDTH];
        bool nb[WIDTH];
        #pragma unroll
        for (int k = 0; k < WIDTH; k++) {
            int idx = nbase + k * stride;
            nb[k] = (idx < n2);
            if (nb[k]) nv[k] = x2[idx];
        }

        // compute + store current stage
        #pragma unroll
        for (int k = 0; k < WIDTH; k++) {
            if (a[k]) out[base + k * stride] = two_rows_exp(sw, v[k], bias);
        }

        if (!nb[0]) break;
        base = nbase;
        #pragma unroll
        for (int k = 0; k < WIDTH; k++) { v[k] = nv[k]; a[k] = nb[k]; }
    }
}

// Rare odd-row tail (B is even in this dataset).
__global__ void lr_tail_kernel(
    const int2* __restrict__ x,
    const float* __restrict__ w,
    const float* __restrict__ bptr,
    float2* __restrict__ out,
    int start, int n)
{
    int i = start + blockIdx.x * blockDim.x + threadIdx.x;
    if (i >= n) return;
    int2 v = x[i];
    float l = __ldg(w + v.x) + __ldg(w + N_USERS + v.y) + __ldg(bptr);
    float e = __expf(-l);
    float p = __frcp_rn(1.0f + e);
    out[i] = make_float2(e * p, p);
}

extern "C" void kernel_launch(void* const* d_in, const int* in_sizes, int n_in,
                              void* d_out, int out_size)
{
    const int*   x = (const int*)d_in[0];     // [B, 2] int32
    const float* W = (const float*)d_in[1];   // [1, 9923]
    const float* b = (const float*)d_in[2];   // [1]
    float* out = (float*)d_out;               // [B, 2]

    int B  = in_sizes[0] / 2;
    int n2 = B / 2;

    if (n2 > 0) {
        int max_blocks = 148 * NBLK_SM;       // 296
        int blocks = (n2 + NTHREADS - 1) / NTHREADS;
        if (blocks > max_blocks) blocks = max_blocks;
        lr_smem_kernel<<<blocks, NTHREADS>>>(
            (const int4*)x, W, b, (float4*)out, n2);
    }
    if (B & 1) {
        lr_tail_kernel<<<1, 32>>>(
            (const int2*)x, W, b, (float2*)out, 2 * n2, B);
    }
}

// round 14
// speedup vs baseline: 1.1517x; 1.0257x over previous
#include <cuda_runtime.h>

// LR_23029614641373: logit = W[u] + W[6040+m] + b; out = [1-p, p]
// Skeleton = R13 verbatim (wall 12.8us best): width-4 software pipeline,
// 512 thr, 2 blocks/SM, SMEM table. SINGLE CHANGE: algebraic folds into
// the table so sigmoid is 5 instrs/row:
//   sw[i] = -log2(e)*(w[i] + b/2)         (bias + exp prescale folded)
//   s  = sw[u] + sw[m']                    (FADD)
//   e  = 2^s = exp(-logit)                 (MUFU ex2.approx)
//   p  = rcp(1+e)                          (FADD + MUFU rcp.approx)
//   1-p = e*p                              (FMUL)
// rcp/ex2 approx err ~1ulp; rel-err budget 1e-3 (headroom ~1e-7).

#define N_USERS 6040
#define TABLE   9923
#define NTHREADS 512
#define NBLK_SM  2
#define WIDTH    4

__device__ __forceinline__ float ex2_fast(float x) {
    float y; asm("ex2.approx.f32 %0, %1;" : "=f"(y) : "f"(x)); return y;
}
__device__ __forceinline__ float rcp_fast(float x) {
    float y; asm("rcp.approx.f32 %0, %1;" : "=f"(y) : "f"(x)); return y;
}

__device__ __forceinline__ float4 two_rows_exp(const float* __restrict__ sw,
                                               int4 v) {
    float s0 = sw[v.x] + sw[N_USERS + v.y];   // = -logit0 * log2(e)
    float s1 = sw[v.z] + sw[N_USERS + v.w];
    float e0 = ex2_fast(s0);                  // = exp(-logit0)
    float e1 = ex2_fast(s1);
    float p0 = rcp_fast(1.0f + e0);
    float p1 = rcp_fast(1.0f + e1);
    return make_float4(e0 * p0, p0, e1 * p1, p1);
}

__global__ void __launch_bounds__(NTHREADS, NBLK_SM) lr_smem_kernel(
    const int4* __restrict__ x2,      // [n2] two (u,m) rows per int4
    const float* __restrict__ w,      // [9923]
    const float* __restrict__ bptr,   // [1]
    float4* __restrict__ out,         // [n2] {1-p0,p0,1-p1,p1}
    int n2)
{
    __shared__ float sw[TABLE];
    {
        const float k = -1.44269504088896340736f;   // -log2(e)
        const float hb = 0.5f * __ldg(bptr);
        #pragma unroll
        for (int i = threadIdx.x; i < TABLE; i += NTHREADS)
            sw[i] = k * (w[i] + hb);
    }
    __syncthreads();

    const int stride = gridDim.x * blockDim.x;

    int base = blockIdx.x * blockDim.x + threadIdx.x;
    if (base >= n2) return;

    int4 v[WIDTH];
    bool a[WIDTH];
    #pragma unroll
    for (int k = 0; k < WIDTH; k++) {
        int idx = base + k * stride;
        a[k] = (idx < n2);
        if (a[k]) v[k] = x2[idx];
    }

    while (true) {
        int nbase = base + WIDTH * stride;

        int4 nv[WIDTH];
        bool nb[WIDTH];
        #pragma unroll
        for (int k = 0; k < WIDTH; k++) {
            int idx = nbase + k * stride;
            nb[k] = (idx < n2);
            if (nb[k]) nv[k] = x2[idx];
        }

        #pragma unroll
        for (int k = 0; k < WIDTH; k++) {
            if (a[k]) out[base + k * stride] = two_rows_exp(sw, v[k]);
        }

        if (!nb[0]) break;
        base = nbase;
        #pragma unroll
        for (int k = 0; k < WIDTH; k++) { v[k] = nv[k]; a[k] = nb[k]; }
    }
}

// Rare odd-row tail (B is even in this dataset).
__global__ void lr_tail_kernel(
    const int2* __restrict__ x,
    const float* __restrict__ w,
    const float* __restrict__ bptr,
    float2* __restrict__ out,
    int start, int n)
{
    int i = start + blockIdx.x * blockDim.x + threadIdx.x;
    if (i >= n) return;
    int2 v = x[i];
    float l = __ldg(w + v.x) + __ldg(w + N_USERS + v.y) + __ldg(bptr);
    float e = ex2_fast(-1.44269504088896340736f * l);
    float p = rcp_fast(1.0f + e);
    out[i] = make_float2(e * p, p);
}

extern "C" void kernel_launch(void* const* d_in, const int* in_sizes, int n_in,
                              void* d_out, int out_size)
{
    const int*   x = (const int*)d_in[0];     // [B, 2] int32
    const float* W = (const float*)d_in[1];   // [1, 9923]
    const float* b = (const float*)d_in[2];   // [1]
    float* out = (float*)d_out;               // [B, 2]

    int B  = in_sizes[0] / 2;
    int n2 = B / 2;

    if (n2 > 0) {
        int max_blocks = 148 * NBLK_SM;       // 296
        int blocks = (n2 + NTHREADS - 1) / NTHREADS;
        if (blocks > max_blocks) blocks = max_blocks;
        lr_smem_kernel<<<blocks, NTHREADS>>>(
            (const int4*)x, W, b, (float4*)out, n2);
    }
    if (B & 1) {
        lr_tail_kernel<<<1, 32>>>(
            (const int2*)x, W, b, (float2*)out, 2 * n2, B);
    }
}